// round 1
// baseline (speedup 1.0000x reference)
#include <cuda_runtime.h>
#include <cstdint>

#define NXg   240
#define NPAD  256
#define CN    8      // cluster size (CTAs)
#define RPC   30     // rows per CTA (240/8)
#define NTH   256
#define NW    8      // warps per CTA
#define FFACf 0.4f

struct Smem {
    float kin [RPC][NPAD];     // local rows of kin, cols padded w/ zeros
    float vint[RPC][NPAD];     // local rows of Vint
    float wbuf[2][2][NPAD];    // ping-pong full wavefunctions w0,w1 (replicated)
    float uho [NPAD];
    float wfb0[32];
    float wfb1[32];
    float udirs[32];
    float warpred[NW][8];
    float redslot[CN][12];     // cluster all-reduce slots (rank-major)
};

__device__ __forceinline__ uint32_t smem_u32(const void* p) {
    return (uint32_t)__cvta_generic_to_shared(p);
}
__device__ __forceinline__ void st_cluster_f32(uint32_t laddr, int rank, float v) {
    uint32_t r;
    asm volatile("mapa.shared::cluster.u32 %0, %1, %2;" : "=r"(r) : "r"(laddr), "r"(rank));
    asm volatile("st.shared::cluster.u32 [%0], %1;" :: "r"(r), "r"(__float_as_uint(v)) : "memory");
}
#define CLUSTER_SYNC() do { \
    asm volatile("barrier.cluster.arrive.aligned;" ::: "memory"); \
    asm volatile("barrier.cluster.wait.aligned;"   ::: "memory"); \
} while (0)

__device__ __forceinline__ float wred(float v) {
    v += __shfl_xor_sync(0xFFFFFFFFu, v, 16);
    v += __shfl_xor_sync(0xFFFFFFFFu, v, 8);
    v += __shfl_xor_sync(0xFFFFFFFFu, v, 4);
    v += __shfl_xor_sync(0xFFFFFFFFu, v, 2);
    v += __shfl_xor_sync(0xFFFFFFFFu, v, 1);
    return v;
}
__device__ __forceinline__ float4 m4(const float4 a, const float4 b) {
    return make_float4(a.x*b.x, a.y*b.y, a.z*b.z, a.w*b.w);
}
__device__ __forceinline__ float dot8(const float4 a0, const float4 a1,
                                      const float4 b0, const float4 b1) {
    float s = a0.x*b0.x;
    s = fmaf(a0.y, b0.y, s); s = fmaf(a0.z, b0.z, s); s = fmaf(a0.w, b0.w, s);
    s = fmaf(a1.x, b1.x, s); s = fmaf(a1.y, b1.y, s);
    s = fmaf(a1.z, b1.z, s); s = fmaf(a1.w, b1.w, s);
    return s;
}

__global__ void __launch_bounds__(NTH, 1) __cluster_dims__(CN, 1, 1)
hf_kernel(const float* __restrict__ wfy0, const float* __restrict__ kin,
          const float* __restrict__ vint, const float* __restrict__ uho,
          const float* __restrict__ delx_p, const float* __restrict__ pfac_p,
          const int* __restrict__ iter_p, float* __restrict__ out)
{
    extern __shared__ char smraw[];
    Smem* s = reinterpret_cast<Smem*>(smraw);
    const int tid  = threadIdx.x;
    const int wid  = tid >> 5;
    const int lane = tid & 31;
    uint32_t rank;
    asm("mov.u32 %0, %%cluster_ctarank;" : "=r"(rank));
    const int row0 = (int)rank * RPC;
    const float delx = *delx_p;
    const float pfac = *pfac_p;
    const int itermax = *iter_p;   // low 32 bits; works for i32 or LE i64

    // ---- init: matrices (local rows) + vectors (full, replicated) into SMEM ----
    for (int i = tid; i < RPC * NPAD; i += NTH) {
        int r = i >> 8, c = i & 255;
        s->kin [r][c] = (c < NXg) ? kin [(row0 + r) * NXg + c] : 0.f;
        s->vint[r][c] = (c < NXg) ? vint[(row0 + r) * NXg + c] : 0.f;
    }
    for (int c = tid; c < NPAD; c += NTH) {
        float a = (c < NXg) ? wfy0[c * 2 + 0] : 0.f;
        float b = (c < NXg) ? wfy0[c * 2 + 1] : 0.f;
        s->wbuf[0][0][c] = a;  s->wbuf[0][1][c] = b;
        s->wbuf[1][0][c] = 0.f; s->wbuf[1][1][c] = 0.f;
        s->uho[c] = (c < NXg) ? uho[c] : 0.f;
    }
    __syncthreads();
    CLUSTER_SYNC();

    const int cbase = lane * 8;   // each lane owns 8 fixed columns

    for (int it = 0; it < itermax; ++it) {
        const int cur = it & 1, nxt = cur ^ 1;
        const float* w0 = s->wbuf[cur][0];
        const float* w1 = s->wbuf[cur][1];

        // lane-resident RHS vectors: w0, w1, w0*w0, w0*w1, w1*w1
        float4 A0 = *(const float4*)(w0 + cbase), A1 = *(const float4*)(w0 + cbase + 4);
        float4 B0 = *(const float4*)(w1 + cbase), B1 = *(const float4*)(w1 + cbase + 4);
        float4 C0 = m4(A0, A0), C1 = m4(A1, A1);
        float4 D0 = m4(A0, B0), D1 = m4(A1, B1);
        float4 E0 = m4(B0, B0), E1 = m4(B1, B1);

        // ---- fused 5-column matvec over local rows (warp-per-row) ----
        float pS0 = 0, pS1 = 0, pSp0 = 0, pSp1 = 0, pEho = 0;
        for (int r = wid; r < RPC; r += NW) {
            const float* kr = s->kin[r];
            const float* vr = s->vint[r];
            float4 K0 = *(const float4*)(kr + cbase), K1 = *(const float4*)(kr + cbase + 4);
            float4 V0 = *(const float4*)(vr + cbase), V1 = *(const float4*)(vr + cbase + 4);
            float kw0 = dot8(K0, K1, A0, A1);
            float kw1 = dot8(K0, K1, B0, B1);
            float v00 = dot8(V0, V1, C0, C1);
            float v01 = dot8(V0, V1, D0, D1);
            float v11 = dot8(V0, V1, E0, E1);
            kw0 = wred(kw0); kw1 = wred(kw1);
            v00 = wred(v00); v01 = wred(v01); v11 = wred(v11);
            if (lane == 0) {
                int gi = row0 + r;
                float w0i = w0[gi], w1i = w1[gi], uh = s->uho[gi];
                float ud  = delx * (v00 + v11);                     // Udir_i
                float hw0 = kw0 - delx * (w0i * v00 + w1i * v01) + (ud + uh) * w0i;
                float hw1 = kw1 - delx * (w0i * v01 + w1i * v11) + (ud + uh) * w1i;
                float fb0 = w0i - pfac * hw0;
                float fb1 = w1i - pfac * hw1;
                s->wfb0[r] = fb0; s->wfb1[r] = fb1; s->udirs[r] = ud;
                pS0  = fmaf(fb0, fb0, pS0);  pS1  = fmaf(fb1, fb1, pS1);
                pSp0 = fmaf(w0i, hw0, pSp0); pSp1 = fmaf(w1i, hw1, pSp1);
                pEho = fmaf(w0i * w0i + w1i * w1i, uh, pEho);
            }
        }
        if (lane == 0) {
            s->warpred[wid][0] = pS0;  s->warpred[wid][1] = pS1;
            s->warpred[wid][2] = pSp0; s->warpred[wid][3] = pSp1;
            s->warpred[wid][4] = pEho;
        }
        __syncthreads();
        if (tid < 5) {
            float v = 0;
            #pragma unroll
            for (int w = 0; w < NW; ++w) v += s->warpred[w][tid];
            uint32_t la = smem_u32(&s->redslot[rank][tid]);
            #pragma unroll
            for (int tr = 0; tr < CN; ++tr) st_cluster_f32(la, tr, v);
        }
        CLUSTER_SYNC();                                   // R1
        float S0 = 0, S1 = 0, SP0 = 0, SP1 = 0, EHO = 0;
        #pragma unroll
        for (int rr = 0; rr < CN; ++rr) {
            S0  += s->redslot[rr][0]; S1  += s->redslot[rr][1];
            SP0 += s->redslot[rr][2]; SP1 += s->redslot[rr][3];
            EHO += s->redslot[rr][4];
        }

        // ---- orbital 0 normalization + Gram-Schmidt prep (warp 0) ----
        float inv0 = 1.f / sqrtf(S0 * delx);
        float inv1 = 1.f / sqrtf(S1 * delx);
        float f0 = 0.f, f1 = 0.f, w0i = 0.f;
        if (wid == 0) {
            float t0p = 0, ap = 0, bp = 0;
            if (lane < RPC) {
                f0  = s->wfb0[lane] * inv0;
                f1  = s->wfb1[lane] * inv1;
                w0i = w0[row0 + lane];
                t0p = f0 * f0; ap = f0 * f1; bp = w0i * f1;
            }
            t0p = wred(t0p); ap = wred(ap); bp = wred(bp);
            if (lane < 3) {
                float v = (lane == 0) ? t0p : ((lane == 1) ? ap : bp);
                uint32_t la = smem_u32(&s->redslot[rank][5 + lane]);
                #pragma unroll
                for (int tr = 0; tr < CN; ++tr) st_cluster_f32(la, tr, v);
            }
        }
        CLUSTER_SYNC();                                   // R2
        float T0 = 0, Aq = 0, Bq = 0;
        #pragma unroll
        for (int rr = 0; rr < CN; ++rr) {
            T0 += s->redslot[rr][5]; Aq += s->redslot[rr][6]; Bq += s->redslot[rr][7];
        }

        float T0d = T0 * delx;
        // d = new0 @ wff1, expanded so it needs no extra reduction round
        float dGS = FFACf * Aq / T0d + (1.f - FFACf) * Bq;
        float n0 = 0.f, f1p = 0.f;
        if (wid == 0) {
            float t1p = 0;
            if (lane < RPC) {
                float wf0f = f0 / T0d;
                n0  = FFACf * wf0f + (1.f - FFACf) * w0i;
                f1p = f1 - n0 * dGS * delx;
                t1p = f1p * f1p;
            }
            t1p = wred(t1p);
            if (lane == 0) {
                uint32_t la = smem_u32(&s->redslot[rank][8]);
                #pragma unroll
                for (int tr = 0; tr < CN; ++tr) st_cluster_f32(la, tr, t1p);
            }
        }
        CLUSTER_SYNC();                                   // R3
        float T1 = 0;
        #pragma unroll
        for (int rr = 0; rr < CN; ++rr) T1 += s->redslot[rr][8];
        float T1d = T1 * delx;

        // ---- finalize new orbitals + broadcast local rows to all ranks ----
        if (wid == 0 && lane < RPC) {
            float n1 = FFACf * (f1p / T1d) + (1.f - FFACf) * w1[row0 + lane];
            uint32_t la0 = smem_u32(&s->wbuf[nxt][0][row0 + lane]);
            uint32_t la1 = smem_u32(&s->wbuf[nxt][1][row0 + lane]);
            #pragma unroll
            for (int tr = 0; tr < CN; ++tr) {
                st_cluster_f32(la0, tr, n0);
                st_cluster_f32(la1, tr, n1);
            }
        }
        CLUSTER_SYNC();                                   // R4

        // ---- final-iteration energies: ekin, epot (one extra 6-col matvec) ----
        if (it == itermax - 1) {
            const float* nv0 = s->wbuf[nxt][0];
            const float* nv1 = s->wbuf[nxt][1];
            float4 N00 = *(const float4*)(nv0 + cbase), N01 = *(const float4*)(nv0 + cbase + 4);
            float4 N10 = *(const float4*)(nv1 + cbase), N11 = *(const float4*)(nv1 + cbase + 4);
            float4 P00 = m4(A0, N00), P01 = m4(A1, N01);   // wold0*new0
            float4 P10 = m4(B0, N00), P11 = m4(B1, N01);   // wold1*new0
            float4 Q00 = m4(A0, N10), Q01 = m4(A1, N11);   // wold0*new1
            float4 Q10 = m4(B0, N10), Q11 = m4(B1, N11);   // wold1*new1
            float pek = 0, pep = 0;
            for (int r = wid; r < RPC; r += NW) {
                const float* kr = s->kin[r];
                const float* vr = s->vint[r];
                float4 K0 = *(const float4*)(kr + cbase), K1 = *(const float4*)(kr + cbase + 4);
                float4 V0 = *(const float4*)(vr + cbase), V1 = *(const float4*)(vr + cbase + 4);
                float kn0 = dot8(K0, K1, N00, N01);
                float kn1 = dot8(K0, K1, N10, N11);
                float q00 = dot8(V0, V1, P00, P01);
                float q10 = dot8(V0, V1, P10, P11);
                float q01 = dot8(V0, V1, Q00, Q01);
                float q11 = dot8(V0, V1, Q10, Q11);
                kn0 = wred(kn0); kn1 = wred(kn1);
                q00 = wred(q00); q10 = wred(q10); q01 = wred(q01); q11 = wred(q11);
                if (lane == 0) {
                    int gi = row0 + r;
                    float n0i = nv0[gi], n1i = nv1[gi];
                    float w0o = w0[gi],  w1o = w1[gi];
                    float diag = s->udirs[r] + s->uho[gi];
                    float um0 = -delx * (w0o * q00 + w1o * q10) + diag * n0i;
                    float um1 = -delx * (w0o * q01 + w1o * q11) + diag * n1i;
                    pek += n0i * kn0 + n1i * kn1;
                    pep += n0i * um0 + n1i * um1;
                }
            }
            if (lane == 0) { s->warpred[wid][5] = pek; s->warpred[wid][6] = pep; }
            __syncthreads();
            if (tid < 2) {
                float v = 0;
                #pragma unroll
                for (int w = 0; w < NW; ++w) v += s->warpred[w][5 + tid];
                uint32_t la = smem_u32(&s->redslot[rank][9 + tid]);
                #pragma unroll
                for (int tr = 0; tr < CN; ++tr) st_cluster_f32(la, tr, v);
            }
            CLUSTER_SYNC();
            if (rank == 0 && tid == 0) {
                float EK = 0, EP = 0;
                for (int rr = 0; rr < CN; ++rr) {
                    EK += s->redslot[rr][9]; EP += s->redslot[rr][10];
                }
                float spe0 = SP0 * delx, spe1 = SP1 * delx;
                float ekin = EK * delx, epot = EP * delx;
                float eho  = EHO * delx * 0.5f;
                float esum = spe0 + spe1;
                float enerhfp = (esum + ekin) * 0.5f + eho;
                float epot0   = epot - 2.f * eho;
                float enerhf  = esum - epot0 * 0.5f;
                out[0] = enerhf; out[1] = enerhfp; out[2] = ekin;
                out[3] = eho;    out[4] = epot0;   out[5] = esum;
            }
        }
    }
}

extern "C" void kernel_launch(void* const* d_in, const int* in_sizes, int n_in,
                              void* d_out, int out_size) {
    (void)in_sizes; (void)n_in; (void)out_size;
    cudaFuncSetAttribute(hf_kernel, cudaFuncAttributeMaxDynamicSharedMemorySize,
                         (int)sizeof(Smem));
    hf_kernel<<<CN, NTH, sizeof(Smem)>>>(
        (const float*)d_in[0],   // wfy0 (240,2)
        (const float*)d_in[1],   // kin_mat (240,240)
        (const float*)d_in[2],   // Vint (240,240)
        (const float*)d_in[3],   // U_HO (240)
        (const float*)d_in[4],   // delx
        (const float*)d_in[5],   // pfac
        (const int*)d_in[6],     // itermax
        (float*)d_out);          // 6 outputs
}

// round 2
// speedup vs baseline: 1.1177x; 1.1177x over previous
#include <cuda_runtime.h>
#include <cstdint>

#define NXg   240
#define NPAD  256
#define CN    8      // cluster size (CTAs)
#define RPC   30     // rows per CTA
#define NTH   256
#define NW    8      // warps per CTA
#define FFACf 0.4f
#define OMFf  0.6f

struct __align__(16) Smem {
    unsigned long long mbar[2];   // ping-pong cluster barriers (count=8)
    float scal[8];
    float udirs[32];
    float wred2[NW][2];
    float redslot[CN][2];
    float uho [NPAD];
    float wbuf [2][2][NPAD];      // ping-pong full 'new' wavefunctions (local)
    float fball[2][2][NPAD];      // ping-pong broadcast wfb vectors (DSMEM-filled)
    float kin [RPC][NPAD];
    float vint[RPC][NPAD];
};

__device__ __forceinline__ uint32_t smem_u32(const void* p) {
    return (uint32_t)__cvta_generic_to_shared(p);
}
__device__ __forceinline__ void st_cluster_f32(uint32_t laddr, int rank, float v) {
    uint32_t r;
    asm volatile("mapa.shared::cluster.u32 %0, %1, %2;" : "=r"(r) : "r"(laddr), "r"(rank));
    asm volatile("st.shared::cluster.u32 [%0], %1;" :: "r"(r), "r"(__float_as_uint(v)) : "memory");
}
__device__ __forceinline__ void mbar_arrive_remote(uint32_t laddr, int rank) {
    asm volatile("{\n\t.reg .b32 ra;\n\t"
        "mapa.shared::cluster.u32 ra, %0, %1;\n\t"
        "mbarrier.arrive.release.cluster.shared::cluster.b64 _, [ra];\n\t}"
        :: "r"(laddr), "r"(rank) : "memory");
}
__device__ __forceinline__ void mbar_wait_parity(uint32_t addr, uint32_t parity) {
    uint32_t done;
    asm volatile("{\n\t.reg .pred p;\n\t"
        "mbarrier.try_wait.parity.acquire.cta.shared::cta.b64 p, [%1], %2;\n\t"
        "selp.b32 %0, 1, 0, p;\n\t}"
        : "=r"(done) : "r"(addr), "r"(parity) : "memory");
    if (!done) {
        asm volatile("{\n\t.reg .pred P1;\n\t"
            "W_%=:\n\t"
            "mbarrier.try_wait.parity.acquire.cta.shared::cta.b64 P1, [%0], %1, 0x989680;\n\t"
            "@P1 bra.uni D_%=;\n\t"
            "bra.uni W_%=;\n\t"
            "D_%=:\n\t}"
            :: "r"(addr), "r"(parity) : "memory");
    }
}
#define CLUSTER_SYNC() do { \
    asm volatile("barrier.cluster.arrive.aligned;" ::: "memory"); \
    asm volatile("barrier.cluster.wait.aligned;"   ::: "memory"); \
} while (0)

__device__ __forceinline__ float wred(float v) {
    v += __shfl_xor_sync(0xFFFFFFFFu, v, 16);
    v += __shfl_xor_sync(0xFFFFFFFFu, v, 8);
    v += __shfl_xor_sync(0xFFFFFFFFu, v, 4);
    v += __shfl_xor_sync(0xFFFFFFFFu, v, 2);
    v += __shfl_xor_sync(0xFFFFFFFFu, v, 1);
    return v;
}

// ---- packed f32x2 helpers (FFMA2 path, PTX-only) ----
__device__ __forceinline__ unsigned long long mul2(unsigned long long a, unsigned long long b) {
    unsigned long long d;
    asm("mul.rn.f32x2 %0, %1, %2;" : "=l"(d) : "l"(a), "l"(b));
    return d;
}
__device__ __forceinline__ unsigned long long fma2(unsigned long long a, unsigned long long b,
                                                   unsigned long long c) {
    unsigned long long d;
    asm("fma.rn.f32x2 %0, %1, %2, %3;" : "=l"(d) : "l"(a), "l"(b), "l"(c));
    return d;
}
__device__ __forceinline__ float hadd2(unsigned long long a) {
    uint32_t lo, hi;
    asm("mov.b64 {%0, %1}, %2;" : "=r"(lo), "=r"(hi) : "l"(a));
    return __uint_as_float(lo) + __uint_as_float(hi);
}
__device__ __forceinline__ float dot4p(const unsigned long long* k, const unsigned long long* x) {
    unsigned long long acc = mul2(k[0], x[0]);
    acc = fma2(k[1], x[1], acc);
    acc = fma2(k[2], x[2], acc);
    acc = fma2(k[3], x[3], acc);
    return hadd2(acc);
}
__device__ __forceinline__ void ld2x2(const float* p, int c1, int c2, unsigned long long* o) {
    ulonglong2 t0 = *reinterpret_cast<const ulonglong2*>(p + c1);
    ulonglong2 t1 = *reinterpret_cast<const ulonglong2*>(p + c2);
    o[0] = t0.x; o[1] = t0.y; o[2] = t1.x; o[3] = t1.y;
}

__global__ void __launch_bounds__(NTH, 1) __cluster_dims__(CN, 1, 1)
hf_kernel(const float* __restrict__ wfy0, const float* __restrict__ kin,
          const float* __restrict__ vint, const float* __restrict__ uho,
          const float* __restrict__ delx_p, const float* __restrict__ pfac_p,
          const int* __restrict__ iter_p, float* __restrict__ out)
{
    extern __shared__ char smraw[];
    Smem* s = reinterpret_cast<Smem*>(smraw);
    const int tid  = threadIdx.x;
    const int wid  = tid >> 5;
    const int lane = tid & 31;
    uint32_t rank;
    asm("mov.u32 %0, %%cluster_ctarank;" : "=r"(rank));
    const int row0 = (int)rank * RPC;
    const float delx = *delx_p;
    const float pfac = *pfac_p;
    const int itermax = *iter_p;

    // ---- init ----
    if (tid == 0) {
        asm volatile("mbarrier.init.shared.b64 [%0], %1;" :: "r"(smem_u32(&s->mbar[0])), "r"(CN) : "memory");
        asm volatile("mbarrier.init.shared.b64 [%0], %1;" :: "r"(smem_u32(&s->mbar[1])), "r"(CN) : "memory");
    }
    for (int i = tid; i < RPC * NPAD; i += NTH) {
        int r = i >> 8, c = i & 255;
        s->kin [r][c] = (c < NXg) ? kin [(row0 + r) * NXg + c] : 0.f;
        s->vint[r][c] = (c < NXg) ? vint[(row0 + r) * NXg + c] : 0.f;
    }
    for (int c = tid; c < NPAD; c += NTH) {
        float a = (c < NXg) ? wfy0[c * 2 + 0] : 0.f;
        float b = (c < NXg) ? wfy0[c * 2 + 1] : 0.f;
        s->wbuf[0][0][c] = a;   s->wbuf[0][1][c] = b;
        s->wbuf[1][0][c] = 0.f; s->wbuf[1][1][c] = 0.f;
        s->fball[0][0][c] = 0.f; s->fball[0][1][c] = 0.f;
        s->fball[1][0][c] = 0.f; s->fball[1][1][c] = 0.f;
        s->uho[c] = (c < NXg) ? uho[c] : 0.f;
    }
    __syncthreads();
    CLUSTER_SYNC();   // mbar init + fball zero visible cluster-wide

    // lane column ownership: [4l,4l+4) and [128+4l,128+4l+4)  (conflict-free LDS.128)
    const int c1 = lane * 4;
    const int c2 = 128 + lane * 4;

    for (int it = 0; it < itermax; ++it) {
        const int cur = it & 1, nx = cur ^ 1;
        const float* w0 = s->wbuf[cur][0];
        const float* w1 = s->wbuf[cur][1];

        // RHS in packed pairs: A=w0, B=w1, C=w0*w0, D=w0*w1, E=w1*w1
        unsigned long long A[4], B[4], C[4], D[4], E[4];
        ld2x2(w0, c1, c2, A);
        ld2x2(w1, c1, c2, B);
        #pragma unroll
        for (int i = 0; i < 4; ++i) {
            C[i] = mul2(A[i], A[i]);
            D[i] = mul2(A[i], B[i]);
            E[i] = mul2(B[i], B[i]);
        }

        // ---- fused 5-col matvec; scatter wfb to all ranks (lanes 0..7) ----
        for (int r = wid; r < RPC; r += NW) {
            unsigned long long K[4], V[4];
            ld2x2(s->kin[r],  c1, c2, K);
            ld2x2(s->vint[r], c1, c2, V);
            float kw0 = dot4p(K, A), kw1 = dot4p(K, B);
            float v00 = dot4p(V, C), v01 = dot4p(V, D), v11 = dot4p(V, E);
            kw0 = wred(kw0); kw1 = wred(kw1);
            v00 = wred(v00); v01 = wred(v01); v11 = wred(v11);
            int gi = row0 + r;
            float w0i = w0[gi], w1i = w1[gi], uh = s->uho[gi];
            float ud  = delx * (v00 + v11);
            float hw0 = kw0 - delx * (w0i * v00 + w1i * v01) + (ud + uh) * w0i;
            float hw1 = kw1 - delx * (w0i * v01 + w1i * v11) + (ud + uh) * w1i;
            float fb0 = w0i - pfac * hw0;
            float fb1 = w1i - pfac * hw1;
            if (lane == 0) s->udirs[r] = ud;
            if (lane < CN) {
                st_cluster_f32(smem_u32(&s->fball[cur][0][gi]), lane, fb0);
                st_cluster_f32(smem_u32(&s->fball[cur][1][gi]), lane, fb1);
            }
        }
        __syncthreads();
        if (tid == 0) {
            uint32_t la = smem_u32(&s->mbar[cur]);
            #pragma unroll
            for (int tr = 0; tr < CN; ++tr) mbar_arrive_remote(la, tr);
        }
        mbar_wait_parity(smem_u32(&s->mbar[cur]), (uint32_t)((it >> 1) & 1));

        // ---- epilogue: warp 0 computes all 9 scalars from full vectors ----
        if (wid == 0) {
            const float* f0a = s->fball[cur][0];
            const float* f1a = s->fball[cur][1];
            float S0=0, S1=0, Xs=0, Ys=0, Zs=0, W2=0, V2=0, Us=0, EH=0;
            #pragma unroll
            for (int g = 0; g < 2; ++g) {
                int c = g ? c2 : c1;
                float4 q0 = *(const float4*)(f0a + c);
                float4 q1 = *(const float4*)(f1a + c);
                float4 p0 = *(const float4*)(w0  + c);
                float4 p1 = *(const float4*)(w1  + c);
                float4 uq = *(const float4*)(s->uho + c);
                #define ACC(F0,F1,P0,P1,UH) do{ \
                    S0 += (F0)*(F0); S1 += (F1)*(F1); Xs += (F0)*(F1); \
                    Ys += (P0)*(F1); Zs += (F0)*(P0); W2 += (P0)*(P0); \
                    V2 += (P1)*(P1); Us += (P1)*(F1); \
                    EH += ((P0)*(P0)+(P1)*(P1))*(UH); }while(0)
                ACC(q0.x,q1.x,p0.x,p1.x,uq.x);
                ACC(q0.y,q1.y,p0.y,p1.y,uq.y);
                ACC(q0.z,q1.z,p0.z,p1.z,uq.z);
                ACC(q0.w,q1.w,p0.w,p1.w,uq.w);
                #undef ACC
            }
            S0 = wred(S0); S1 = wred(S1); Xs = wred(Xs);
            Ys = wred(Ys); Zs = wred(Zs); W2 = wred(W2);
            V2 = wred(V2); Us = wred(Us); EH = wred(EH);
            if (lane == 0) {
                float inv0 = rsqrtf(S0 * delx);
                float inv1 = rsqrtf(S1 * delx);
                float dGS  = FFACf * inv0 * inv1 * Xs + OMFf * inv1 * Ys;
                float sn0  = FFACf * FFACf / delx + 1.2f * FFACf * inv0 * Zs + 0.36f * W2;
                float T1   = 1.f / delx - dGS * dGS * delx * (2.f - delx * sn0);
                float invT1d = 1.f / (T1 * delx);
                s->scal[0] = FFACf * inv0;                 // n0 = a0*fb0 + 0.6*w0
                s->scal[1] = FFACf * invT1d * inv1;        // n1 = b1*fb1 - c1*n0 + 0.6*w1
                s->scal[2] = FFACf * invT1d * dGS * delx;
                s->scal[3] = W2 - Zs;                      // spe0 * pfac / delx
                s->scal[4] = V2 - Us;                      // spe1 * pfac / delx
                s->scal[5] = EH;                           // eho * 2 / delx
            }
        }
        __syncthreads();
        if (tid < NXg) {
            float a0 = s->scal[0], b1 = s->scal[1], cc = s->scal[2];
            float fb0 = s->fball[cur][0][tid];
            float fb1 = s->fball[cur][1][tid];
            float n0 = a0 * fb0 + OMFf * w0[tid];
            float n1 = b1 * fb1 - cc * n0 + OMFf * w1[tid];
            s->wbuf[nx][0][tid] = n0;
            s->wbuf[nx][1][tid] = n1;
        }
        __syncthreads();
    }

    // ---- final energies: ekin = new·K·new, epot = new·Umf·new ----
    {
        const int fin = itermax & 1, oldp = fin ^ 1;
        const float* wo0 = s->wbuf[oldp][0]; const float* wo1 = s->wbuf[oldp][1];
        const float* nv0 = s->wbuf[fin][0];  const float* nv1 = s->wbuf[fin][1];
        unsigned long long Ao[4], Bo[4], N0[4], N1[4], P0[4], P1[4], Q0[4], Q1[4];
        ld2x2(wo0, c1, c2, Ao);
        ld2x2(wo1, c1, c2, Bo);
        ld2x2(nv0, c1, c2, N0);
        ld2x2(nv1, c1, c2, N1);
        #pragma unroll
        for (int i = 0; i < 4; ++i) {
            P0[i] = mul2(Ao[i], N0[i]);
            P1[i] = mul2(Bo[i], N0[i]);
            Q0[i] = mul2(Ao[i], N1[i]);
            Q1[i] = mul2(Bo[i], N1[i]);
        }
        float pek = 0.f, pep = 0.f;
        for (int r = wid; r < RPC; r += NW) {
            unsigned long long K[4], V[4];
            ld2x2(s->kin[r],  c1, c2, K);
            ld2x2(s->vint[r], c1, c2, V);
            float kn0 = dot4p(K, N0), kn1 = dot4p(K, N1);
            float q00 = dot4p(V, P0), q10 = dot4p(V, P1);
            float q01 = dot4p(V, Q0), q11 = dot4p(V, Q1);
            kn0 = wred(kn0); kn1 = wred(kn1);
            q00 = wred(q00); q10 = wred(q10);
            q01 = wred(q01); q11 = wred(q11);
            if (lane == 0) {
                int gi = row0 + r;
                float n0i = nv0[gi], n1i = nv1[gi];
                float w0o = wo0[gi], w1o = wo1[gi];
                float diag = s->udirs[r] + s->uho[gi];
                float um0 = -delx * (w0o * q00 + w1o * q10) + diag * n0i;
                float um1 = -delx * (w0o * q01 + w1o * q11) + diag * n1i;
                pek += n0i * kn0 + n1i * kn1;
                pep += n0i * um0 + n1i * um1;
            }
        }
        if (lane == 0) { s->wred2[wid][0] = pek; s->wred2[wid][1] = pep; }
        __syncthreads();
        if (tid < 2) {
            float v = 0.f;
            #pragma unroll
            for (int w = 0; w < NW; ++w) v += s->wred2[w][tid];
            uint32_t la = smem_u32(&s->redslot[rank][tid]);
            #pragma unroll
            for (int tr = 0; tr < CN; ++tr) st_cluster_f32(la, tr, v);
        }
        CLUSTER_SYNC();
        if (rank == 0 && tid == 0) {
            float EK = 0.f, EP = 0.f;
            for (int rr = 0; rr < CN; ++rr) { EK += s->redslot[rr][0]; EP += s->redslot[rr][1]; }
            float esum = (s->scal[3] + s->scal[4]) / pfac * delx;
            float eho  = s->scal[5] * delx * 0.5f;
            float ekin = EK * delx;
            float epot = EP * delx;
            float enerhfp = (esum + ekin) * 0.5f + eho;
            float epot0   = epot - 2.f * eho;
            float enerhf  = esum - epot0 * 0.5f;
            out[0] = enerhf; out[1] = enerhfp; out[2] = ekin;
            out[3] = eho;    out[4] = epot0;   out[5] = esum;
        }
    }
}

extern "C" void kernel_launch(void* const* d_in, const int* in_sizes, int n_in,
                              void* d_out, int out_size) {
    (void)in_sizes; (void)n_in; (void)out_size;
    cudaFuncSetAttribute(hf_kernel, cudaFuncAttributeMaxDynamicSharedMemorySize,
                         (int)sizeof(Smem));
    hf_kernel<<<CN, NTH, sizeof(Smem)>>>(
        (const float*)d_in[0],   // wfy0 (240,2)
        (const float*)d_in[1],   // kin_mat (240,240)
        (const float*)d_in[2],   // Vint (240,240)
        (const float*)d_in[3],   // U_HO (240)
        (const float*)d_in[4],   // delx
        (const float*)d_in[5],   // pfac
        (const int*)d_in[6],     // itermax
        (float*)d_out);          // 6 outputs
}

// round 3
// speedup vs baseline: 1.9424x; 1.7378x over previous
#include <cuda_runtime.h>
#include <cstdint>

#define NXg   240
#define NPAD  256
#define CN    8      // cluster size (CTAs)
#define RPC   30     // rows per CTA
#define NTH   512
#define NW    16     // warps per CTA
#define FFACf 0.4f
#define OMFf  0.6f
#define PSTR  44     // padded stride for partials (5 dots * 8 + 4 pad)

struct __align__(16) Smem {
    unsigned long long mbar[2];     // ping-pong cluster barriers (count=8)
    float scal[8];
    float udirs[32];
    float fbloc[2][32];             // local fb0/fb1 for this CTA's rows
    float wred2[NW][2];
    float redF[CN][2];              // final-energy cluster slots
    float redslot[2][CN][16];       // ping-pong partial-scalar slots [parity][src][scal]
    float part[RPC][PSTR];          // stage-1 partials
    float uho [NPAD];
    float wbuf [2][2][NPAD];        // ping-pong wavefunctions (local)
    float fball[2][2][NPAD];        // ping-pong broadcast fb vectors (DSMEM-filled)
    float kin [RPC][NPAD];
    float vint[RPC][NPAD];
};

__device__ __forceinline__ uint32_t smem_u32(const void* p) {
    return (uint32_t)__cvta_generic_to_shared(p);
}
__device__ __forceinline__ void st_cluster_f32(uint32_t laddr, int rank, float v) {
    uint32_t r;
    asm volatile("mapa.shared::cluster.u32 %0, %1, %2;" : "=r"(r) : "r"(laddr), "r"(rank));
    asm volatile("st.shared::cluster.u32 [%0], %1;" :: "r"(r), "r"(__float_as_uint(v)) : "memory");
}
__device__ __forceinline__ void mbar_arrive_remote(uint32_t laddr, int rank) {
    asm volatile("{\n\t.reg .b32 ra;\n\t"
        "mapa.shared::cluster.u32 ra, %0, %1;\n\t"
        "mbarrier.arrive.release.cluster.shared::cluster.b64 _, [ra];\n\t}"
        :: "r"(laddr), "r"(rank) : "memory");
}
__device__ __forceinline__ void mbar_wait_parity(uint32_t addr, uint32_t parity) {
    uint32_t done;
    asm volatile("{\n\t.reg .pred p;\n\t"
        "mbarrier.try_wait.parity.acquire.cta.shared::cta.b64 p, [%1], %2;\n\t"
        "selp.b32 %0, 1, 0, p;\n\t}"
        : "=r"(done) : "r"(addr), "r"(parity) : "memory");
    if (!done) {
        asm volatile("{\n\t.reg .pred P1;\n\t"
            "W_%=:\n\t"
            "mbarrier.try_wait.parity.acquire.cta.shared::cta.b64 P1, [%0], %1, 0x989680;\n\t"
            "@P1 bra.uni D_%=;\n\t"
            "bra.uni W_%=;\n\t"
            "D_%=:\n\t}"
            :: "r"(addr), "r"(parity) : "memory");
    }
}
#define CLUSTER_SYNC() do { \
    asm volatile("barrier.cluster.arrive.aligned;" ::: "memory"); \
    asm volatile("barrier.cluster.wait.aligned;"   ::: "memory"); \
} while (0)

__device__ __forceinline__ float wred(float v) {
    v += __shfl_xor_sync(0xFFFFFFFFu, v, 16);
    v += __shfl_xor_sync(0xFFFFFFFFu, v, 8);
    v += __shfl_xor_sync(0xFFFFFFFFu, v, 4);
    v += __shfl_xor_sync(0xFFFFFFFFu, v, 2);
    v += __shfl_xor_sync(0xFFFFFFFFu, v, 1);
    return v;
}
__device__ __forceinline__ float wred2lvl(float v) {   // lanes 0..7 hold 8 partials
    v += __shfl_xor_sync(0xFFFFFFFFu, v, 16);
    v += __shfl_xor_sync(0xFFFFFFFFu, v, 8);
    return v;
}

// ---- packed f32x2 helpers (FFMA2 path, PTX-only) ----
__device__ __forceinline__ unsigned long long mul2(unsigned long long a, unsigned long long b) {
    unsigned long long d;
    asm("mul.rn.f32x2 %0, %1, %2;" : "=l"(d) : "l"(a), "l"(b));
    return d;
}
__device__ __forceinline__ unsigned long long fma2(unsigned long long a, unsigned long long b,
                                                   unsigned long long c) {
    unsigned long long d;
    asm("fma.rn.f32x2 %0, %1, %2, %3;" : "=l"(d) : "l"(a), "l"(b), "l"(c));
    return d;
}
__device__ __forceinline__ float hadd2(unsigned long long a) {
    uint32_t lo, hi;
    asm("mov.b64 {%0, %1}, %2;" : "=r"(lo), "=r"(hi) : "l"(a));
    return __uint_as_float(lo) + __uint_as_float(hi);
}
__device__ __forceinline__ float dot4p(const unsigned long long* k, const unsigned long long* x) {
    unsigned long long acc = mul2(k[0], x[0]);
    acc = fma2(k[1], x[1], acc);
    acc = fma2(k[2], x[2], acc);
    acc = fma2(k[3], x[3], acc);
    return hadd2(acc);
}
__device__ __forceinline__ void ld2x2(const float* p, int c1, int c2, unsigned long long* o) {
    ulonglong2 t0 = *reinterpret_cast<const ulonglong2*>(p + c1);
    ulonglong2 t1 = *reinterpret_cast<const ulonglong2*>(p + c2);
    o[0] = t0.x; o[1] = t0.y; o[2] = t1.x; o[3] = t1.y;
}
__device__ __forceinline__ float sum8(const float* p) {
    float4 a = *(const float4*)p;
    float4 b = *(const float4*)(p + 4);
    return ((a.x + a.y) + (a.z + a.w)) + ((b.x + b.y) + (b.z + b.w));
}

__global__ void __launch_bounds__(NTH, 1) __cluster_dims__(CN, 1, 1)
hf_kernel(const float* __restrict__ wfy0, const float* __restrict__ kin,
          const float* __restrict__ vint, const float* __restrict__ uho,
          const float* __restrict__ delx_p, const float* __restrict__ pfac_p,
          const int* __restrict__ iter_p, float* __restrict__ out)
{
    extern __shared__ char smraw[];
    Smem* s = reinterpret_cast<Smem*>(smraw);
    const int tid  = threadIdx.x;
    const int wid  = tid >> 5;
    const int lane = tid & 31;
    uint32_t rank;
    asm("mov.u32 %0, %%cluster_ctarank;" : "=r"(rank));
    const int row0 = (int)rank * RPC;
    const float delx = *delx_p;
    const float pfac = *pfac_p;
    const float rdelx = 1.f / delx;
    const int itermax = *iter_p;

    // ---- init ----
    if (tid == 0) {
        asm volatile("mbarrier.init.shared.b64 [%0], %1;" :: "r"(smem_u32(&s->mbar[0])), "r"(CN) : "memory");
        asm volatile("mbarrier.init.shared.b64 [%0], %1;" :: "r"(smem_u32(&s->mbar[1])), "r"(CN) : "memory");
    }
    for (int i = tid; i < RPC * NPAD; i += NTH) {
        int r = i >> 8, c = i & 255;
        s->kin [r][c] = (c < NXg) ? kin [(row0 + r) * NXg + c] : 0.f;
        s->vint[r][c] = (c < NXg) ? vint[(row0 + r) * NXg + c] : 0.f;
    }
    for (int c = tid; c < NPAD; c += NTH) {
        float a = (c < NXg) ? wfy0[c * 2 + 0] : 0.f;
        float b = (c < NXg) ? wfy0[c * 2 + 1] : 0.f;
        s->wbuf[0][0][c] = a;   s->wbuf[0][1][c] = b;
        s->wbuf[1][0][c] = 0.f; s->wbuf[1][1][c] = 0.f;
        s->uho[c] = (c < NXg) ? uho[c] : 0.f;
    }
    __syncthreads();
    CLUSTER_SYNC();   // mbar init visible cluster-wide

    // lane column ownership: [4l,4l+4) and [128+4l,128+4l+4)  (conflict-free LDS.128)
    const int c1 = lane * 4;
    const int c2 = 128 + lane * 4;

    for (int it = 0; it < itermax; ++it) {
        const int cur = it & 1, nx = cur ^ 1;
        const float* w0 = s->wbuf[cur][0];
        const float* w1 = s->wbuf[cur][1];

        // RHS in packed pairs: A=w0, B=w1, C=w0*w0, D=w0*w1, E=w1*w1
        unsigned long long A[4], B[4], C[4], D[4], E[4];
        ld2x2(w0, c1, c2, A);
        ld2x2(w1, c1, c2, B);
        #pragma unroll
        for (int i = 0; i < 4; ++i) {
            C[i] = mul2(A[i], A[i]);
            D[i] = mul2(A[i], B[i]);
            E[i] = mul2(B[i], B[i]);
        }

        // ---- stage 1: 5-col matvec partials (warp-per-row, 2-level reduce) ----
        for (int r = wid; r < RPC; r += NW) {
            unsigned long long K[4], V[4];
            ld2x2(s->kin[r],  c1, c2, K);
            ld2x2(s->vint[r], c1, c2, V);
            float kw0 = dot4p(K, A), kw1 = dot4p(K, B);
            float v00 = dot4p(V, C), v01 = dot4p(V, D), v11 = dot4p(V, E);
            kw0 = wred2lvl(kw0); kw1 = wred2lvl(kw1);
            v00 = wred2lvl(v00); v01 = wred2lvl(v01); v11 = wred2lvl(v11);
            if (lane < 8) {
                float* pr = s->part[r];
                pr[ 0 + lane] = kw0;
                pr[ 8 + lane] = kw1;
                pr[16 + lane] = v00;
                pr[24 + lane] = v01;
                pr[32 + lane] = v11;
            }
        }
        __syncthreads();                                  // bar1

        // ---- stage 2: thread-per-row finish (warp 0) ----
        if (wid == 0 && lane < RPC) {
            const float* pr = s->part[lane];
            float kw0 = sum8(pr +  0);
            float kw1 = sum8(pr +  8);
            float v00 = sum8(pr + 16);
            float v01 = sum8(pr + 24);
            float v11 = sum8(pr + 32);
            int gi = row0 + lane;
            float w0i = w0[gi], w1i = w1[gi], uh = s->uho[gi];
            float ud  = delx * (v00 + v11);
            float hw0 = kw0 - delx * (w0i * v00 + w1i * v01) + (ud + uh) * w0i;
            float hw1 = kw1 - delx * (w0i * v01 + w1i * v11) + (ud + uh) * w1i;
            s->fbloc[0][lane] = w0i - pfac * hw0;
            s->fbloc[1][lane] = w1i - pfac * hw1;
            s->udirs[lane] = ud;
        }
        __syncthreads();                                  // bar2

        // ---- scatter fb to all ranks (warps 0-7) + partial scalars (warps 8-15) ----
        if (wid < 8) {
            if (tid < 240) {
                int row = tid >> 3, rk = tid & 7, gi = row0 + row;
                float f0 = s->fbloc[0][row];
                float f1 = s->fbloc[1][row];
                st_cluster_f32(smem_u32(&s->fball[cur][0][gi]), rk, f0);
                st_cluster_f32(smem_u32(&s->fball[cur][1][gi]), rk, f1);
            }
        } else {
            int sid = wid - 8;
            float fb0 = 0.f, fb1 = 0.f, w0i = 0.f, w1i = 0.f, uh = 0.f;
            if (lane < RPC) {
                fb0 = s->fbloc[0][lane]; fb1 = s->fbloc[1][lane];
                int gi = row0 + lane;
                w0i = w0[gi]; w1i = w1[gi]; uh = s->uho[gi];
            }
            float v;
            if      (sid == 0) v = fb0 * fb0;   // S0
            else if (sid == 1) v = fb1 * fb1;   // S1
            else if (sid == 2) v = fb0 * fb1;   // Xs
            else if (sid == 3) v = w0i * fb1;   // Ys
            else if (sid == 4) v = fb0 * w0i;   // Zs
            else if (sid == 5) v = w0i * w0i;   // W2
            else if (sid == 6) v = w1i * w1i;   // V2
            else               v = w1i * fb1;   // Us
            v = wred(v);
            if (lane == 0) {
                uint32_t la = smem_u32(&s->redslot[cur][rank][sid]);
                #pragma unroll
                for (int rk = 0; rk < CN; ++rk) st_cluster_f32(la, rk, v);
            }
            if (sid == 0) {
                float e = (w0i * w0i + w1i * w1i) * uh;   // EH
                e = wred(e);
                if (lane == 0) {
                    uint32_t la = smem_u32(&s->redslot[cur][rank][8]);
                    #pragma unroll
                    for (int rk = 0; rk < CN; ++rk) st_cluster_f32(la, rk, e);
                }
            }
        }
        __syncthreads();                                  // bar3
        if (tid < CN) mbar_arrive_remote(smem_u32(&s->mbar[cur]), tid);
        mbar_wait_parity(smem_u32(&s->mbar[cur]), (uint32_t)((it >> 1) & 1));

        // ---- post-sync: combine 9 scalars, closed-form chain (warp 0) ----
        if (wid == 0) {
            float T = 0.f;
            if (lane < 9) {
                #pragma unroll
                for (int rr = 0; rr < CN; ++rr) T += s->redslot[cur][rr][lane];
            }
            float S0 = __shfl_sync(0xFFFFFFFFu, T, 0);
            float S1 = __shfl_sync(0xFFFFFFFFu, T, 1);
            float Xs = __shfl_sync(0xFFFFFFFFu, T, 2);
            float Ys = __shfl_sync(0xFFFFFFFFu, T, 3);
            float Zs = __shfl_sync(0xFFFFFFFFu, T, 4);
            float W2 = __shfl_sync(0xFFFFFFFFu, T, 5);
            float V2 = __shfl_sync(0xFFFFFFFFu, T, 6);
            float Us = __shfl_sync(0xFFFFFFFFu, T, 7);
            float EH = __shfl_sync(0xFFFFFFFFu, T, 8);
            if (lane == 0) {
                float inv0 = rsqrtf(S0 * delx);
                float inv1 = rsqrtf(S1 * delx);
                float dGS  = FFACf * inv0 * inv1 * Xs + OMFf * inv1 * Ys;
                float sn0  = 0.16f * rdelx + 0.48f * inv0 * Zs + 0.36f * W2;
                float T1   = rdelx - dGS * dGS * delx * (2.f - delx * sn0);
                float invT1d = __fdividef(1.f, T1 * delx);
                s->scal[0] = FFACf * inv0;
                s->scal[1] = FFACf * invT1d * inv1;
                s->scal[2] = FFACf * invT1d * dGS * delx;
                s->scal[3] = W2 - Zs;                      // spe0 * pfac / delx
                s->scal[4] = V2 - Us;                      // spe1 * pfac / delx
                s->scal[5] = EH;                           // eho * 2 / delx
            }
        }
        __syncthreads();                                  // bar4
        if (tid < NXg) {
            float a0 = s->scal[0], b1 = s->scal[1], cc = s->scal[2];
            float fb0 = s->fball[cur][0][tid];
            float fb1 = s->fball[cur][1][tid];
            float n0 = a0 * fb0 + OMFf * w0[tid];
            float n1 = b1 * fb1 - cc * n0 + OMFf * w1[tid];
            s->wbuf[nx][0][tid] = n0;
            s->wbuf[nx][1][tid] = n1;
        }
        __syncthreads();                                  // bar5
    }

    // ---- final energies: ekin = new.K.new, epot = new.Umf.new ----
    {
        const int fin = itermax & 1, oldp = fin ^ 1;
        const float* wo0 = s->wbuf[oldp][0]; const float* wo1 = s->wbuf[oldp][1];
        const float* nv0 = s->wbuf[fin][0];  const float* nv1 = s->wbuf[fin][1];
        unsigned long long Ao[4], Bo[4], N0[4], N1[4], P0[4], P1[4], Q0[4], Q1[4];
        ld2x2(wo0, c1, c2, Ao);
        ld2x2(wo1, c1, c2, Bo);
        ld2x2(nv0, c1, c2, N0);
        ld2x2(nv1, c1, c2, N1);
        #pragma unroll
        for (int i = 0; i < 4; ++i) {
            P0[i] = mul2(Ao[i], N0[i]);
            P1[i] = mul2(Bo[i], N0[i]);
            Q0[i] = mul2(Ao[i], N1[i]);
            Q1[i] = mul2(Bo[i], N1[i]);
        }
        float pek = 0.f, pep = 0.f;
        for (int r = wid; r < RPC; r += NW) {
            unsigned long long K[4], V[4];
            ld2x2(s->kin[r],  c1, c2, K);
            ld2x2(s->vint[r], c1, c2, V);
            float kn0 = dot4p(K, N0), kn1 = dot4p(K, N1);
            float q00 = dot4p(V, P0), q10 = dot4p(V, P1);
            float q01 = dot4p(V, Q0), q11 = dot4p(V, Q1);
            kn0 = wred(kn0); kn1 = wred(kn1);
            q00 = wred(q00); q10 = wred(q10);
            q01 = wred(q01); q11 = wred(q11);
            if (lane == 0) {
                int gi = row0 + r;
                float n0i = nv0[gi], n1i = nv1[gi];
                float w0o = wo0[gi], w1o = wo1[gi];
                float diag = s->udirs[r] + s->uho[gi];
                float um0 = -delx * (w0o * q00 + w1o * q10) + diag * n0i;
                float um1 = -delx * (w0o * q01 + w1o * q11) + diag * n1i;
                pek += n0i * kn0 + n1i * kn1;
                pep += n0i * um0 + n1i * um1;
            }
        }
        if (lane == 0) { s->wred2[wid][0] = pek; s->wred2[wid][1] = pep; }
        __syncthreads();
        if (tid < 2) {
            float v = 0.f;
            #pragma unroll
            for (int w = 0; w < NW; ++w) v += s->wred2[w][tid];
            uint32_t la = smem_u32(&s->redF[rank][tid]);
            #pragma unroll
            for (int tr = 0; tr < CN; ++tr) st_cluster_f32(la, tr, v);
        }
        CLUSTER_SYNC();
        if (rank == 0 && tid == 0) {
            float EK = 0.f, EP = 0.f;
            for (int rr = 0; rr < CN; ++rr) { EK += s->redF[rr][0]; EP += s->redF[rr][1]; }
            float esum = (s->scal[3] + s->scal[4]) / pfac * delx;
            float eho  = s->scal[5] * delx * 0.5f;
            float ekin = EK * delx;
            float epot = EP * delx;
            float enerhfp = (esum + ekin) * 0.5f + eho;
            float epot0   = epot - 2.f * eho;
            float enerhf  = esum - epot0 * 0.5f;
            out[0] = enerhf; out[1] = enerhfp; out[2] = ekin;
            out[3] = eho;    out[4] = epot0;   out[5] = esum;
        }
    }
}

extern "C" void kernel_launch(void* const* d_in, const int* in_sizes, int n_in,
                              void* d_out, int out_size) {
    (void)in_sizes; (void)n_in; (void)out_size;
    cudaFuncSetAttribute(hf_kernel, cudaFuncAttributeMaxDynamicSharedMemorySize,
                         (int)sizeof(Smem));
    hf_kernel<<<CN, NTH, sizeof(Smem)>>>(
        (const float*)d_in[0],   // wfy0 (240,2)
        (const float*)d_in[1],   // kin_mat (240,240)
        (const float*)d_in[2],   // Vint (240,240)
        (const float*)d_in[3],   // U_HO (240)
        (const float*)d_in[4],   // delx
        (const float*)d_in[5],   // pfac
        (const int*)d_in[6],     // itermax
        (float*)d_out);          // 6 outputs
}